// round 12
// baseline (speedup 1.0000x reference)
#include <cuda_runtime.h>

// Problem constants (shapes fixed by dataset; code stays correct for any
// batch_list via the offsets kernel + generic path).
#define D_DIM   300          // embedding dim
#define DC      60           // columns per chunk (multiple of 4, divides 300)
#define DC4     (DC / 4)     // 15 float4 per row-chunk
#define NCHUNK  (D_DIM / DC) // 5
#define TR      256          // row tile (== nodes per graph in this dataset)
#define GT      480          // threads per group = 32 row-blocks * 15 quads
#define NT      960          // threads per CTA = 2 independent groups
#define RB      32           // row-blocks
#define KIT     (TR / RB)    // 8 rows per thread in fast path
#define MAXB    8192
#define EPSV    1e-12f

// Scratch (no cudaMalloc allowed).
__device__ int g_off[MAXB + 1];
__device__ int g_B;
__device__ int g_uni;   // 1 iff all graphs have equal node counts
__device__ int g_uval;  // that count

// ---------------------------------------------------------------------------
// Offsets kernel: detects int32 vs int64 batch_list layout. Uniform fast path
// publishes only {flag, value, count} — no scan, no offset writes. General
// path: block-wide inclusive scan into g_off.
// ---------------------------------------------------------------------------
__global__ void offsets_kernel(const int* __restrict__ p32, int nb, int ntot) {
    __shared__ int sh[1024];
    __shared__ int s_stride, s_carry, s_uni, s_val;
    const int tid = threadIdx.x;

    if (tid == 0) {
        int stride = 1;
        if (nb > 1) {
            int v0 = p32[0], v1 = p32[1];
            if (v1 == 0 && v0 != 0) stride = 2;   // int64 little-endian
        }
        s_stride = stride;
        s_carry = 0;
        s_uni = 1;
        s_val = p32[0];
        g_off[0] = 0;
        g_uni = 0;
    }
    __syncthreads();

    const int st = s_stride;
    int B = nb;
    if (B > MAXB) B = MAXB;
    const int B1 = (st == 2) ? (B >> 1) : B;
    const int v0 = s_val;

    int uni = 1;
    for (int i = tid; i < B1; i += 1024)
        if (p32[(size_t)i * st] != v0) uni = 0;
    if (!uni) atomicAnd(&s_uni, 0);
    __syncthreads();

    if (s_uni && (long long)B1 * v0 == ntot) {
        if (tid == 0) {
            g_B = B1;
            g_uval = v0;
            g_uni = 1;          // main kernel computes offsets arithmetically
        }
        return;
    }

    // ---- general path: inclusive scan into g_off ----
    for (int base = 0; base < B1; base += 1024) {
        int i = base + tid;
        int v = (i < B1) ? p32[(size_t)i * st] : 0;
        sh[tid] = v;
        __syncthreads();
        #pragma unroll
        for (int o = 1; o < 1024; o <<= 1) {
            int t = (tid >= o) ? sh[tid - o] : 0;
            __syncthreads();
            sh[tid] += t;
            __syncthreads();
        }
        if (i < B1) g_off[i + 1] = s_carry + sh[tid];
        __syncthreads();
        if (tid == 0) s_carry += sh[1023];
        __syncthreads();
    }

    int Bfinal = B1;
    if (st == 2 && B1 > 0 && g_off[B1] != ntot && B > B1) {
        for (int base = B1; base < B; base += 1024) {
            int i = base + tid;
            int v = (i < B) ? p32[(size_t)i * st] : 0;
            sh[tid] = v;
            __syncthreads();
            #pragma unroll
            for (int o = 1; o < 1024; o <<= 1) {
                int t = (tid >= o) ? sh[tid - o] : 0;
                __syncthreads();
                sh[tid] += t;
                __syncthreads();
            }
            if (i < B) g_off[i + 1] = s_carry + sh[tid];
            __syncthreads();
            if (tid == 0) s_carry += sh[1023];
            __syncthreads();
        }
        Bfinal = B;
    }
    if (tid == 0) g_B = Bfinal;
}

// ---------------------------------------------------------------------------
// Helpers
// ---------------------------------------------------------------------------
__device__ __forceinline__ float4 min4(float4 a, float4 b) {
    return make_float4(fminf(a.x, b.x), fminf(a.y, b.y),
                       fminf(a.z, b.z), fminf(a.w, b.w));
}
__device__ __forceinline__ float4 max4(float4 a, float4 b) {
    return make_float4(fmaxf(a.x, b.x), fmaxf(a.y, b.y),
                       fmaxf(a.z, b.z), fmaxf(a.w, b.w));
}
// group barrier: named barrier scoped to this group's 480 threads
__device__ __forceinline__ void gbar(int id) {
    asm volatile("bar.sync %0, %1;" :: "r"(id), "r"(GT) : "memory");
}

// ---------------------------------------------------------------------------
// Main kernel: 960 threads/CTA = TWO independent 480-thread groups, 1 CTA/SM.
// Each group processes one (graph, 60-col chunk) tile exactly like R11:
// thread (rb, j) loads 8 rows of its column quad into registers (MLP=8),
// reduces min/max in flight, smem tree fold, normalize from registers.
// Groups synchronize with named barriers (bar.sync 1/2, 480), so when one
// group sits in its fold barriers the other group's loads/stores keep the
// SM's DRAM queue busy — the lockstep bubble of 2x480 CTAs is removed.
// Default cache policy (L2 merges chunk-boundary lines). Single DRAM
// read + single DRAM write of the tensor.
// ---------------------------------------------------------------------------
__global__ void __launch_bounds__(NT, 1)
cube_norm_kernel(const float* __restrict__ x, float* __restrict__ y,
                 int ntiles) {
    __shared__ float4 s_mn[2][RB][DC4];   // per-group partials (2 x 7680 B)
    __shared__ float4 s_mx[2][RB][DC4];

    const int tid  = threadIdx.x;
    const int gid  = tid / GT;            // group 0 or 1
    const int stid = tid - gid * GT;      // 0..479 within group
    const int bar  = gid + 1;             // named barrier id 1 or 2

    const int t = blockIdx.x * 2 + gid;   // this group's tile
    if (t >= ntiles) return;

    const int g  = t / NCHUNK;
    const int c0 = (t - g * NCHUNK) * DC;
    if (g >= g_B) return;

    int r0, nr;
    if (g_uni) {
        nr = g_uval;
        r0 = g * nr;
    } else {
        r0 = g_off[g];
        nr = g_off[g + 1] - r0;
    }
    if (nr <= 0) return;

    const int j  = stid % DC4;            // column quad 0..14
    const int rb = stid / DC4;            // row block 0..31

    const float* xg = x + (size_t)r0 * D_DIM + c0 + 4 * j;
    float*       yg = y + (size_t)r0 * D_DIM + c0 + 4 * j;

    if (nr == TR) {
        // ---------------- fast register-resident path ----------------
        float4 v[KIT];
        const float* p = xg + (size_t)rb * D_DIM;
        #pragma unroll
        for (int k = 0; k < KIT; k++)
            v[k] = *(const float4*)(p + (size_t)k * RB * D_DIM);

        float4 mn = v[0], mx = v[0];
        #pragma unroll
        for (int k = 1; k < KIT; k++) {
            mn = min4(mn, v[k]);
            mx = max4(mx, v[k]);
        }
        s_mn[gid][rb][j] = mn;
        s_mx[gid][rb][j] = mx;
        gbar(bar);

        // tree reduce over row blocks (group-local)
        #pragma unroll
        for (int s = RB / 2; s >= 1; s >>= 1) {
            if (rb < s) {
                s_mn[gid][rb][j] = min4(s_mn[gid][rb][j], s_mn[gid][rb + s][j]);
                s_mx[gid][rb][j] = max4(s_mx[gid][rb][j], s_mx[gid][rb + s][j]);
            }
            gbar(bar);
        }

        float4 fmn = s_mn[gid][0][j];
        float4 fmx = s_mx[gid][0][j];
        float4 mid = make_float4((fmx.x + fmn.x) * 0.5f, (fmx.y + fmn.y) * 0.5f,
                                 (fmx.z + fmn.z) * 0.5f, (fmx.w + fmn.w) * 0.5f);
        float4 inv = make_float4(
            1.0f / fmaxf((fmx.x - fmn.x) * 0.5f, EPSV),
            1.0f / fmaxf((fmx.y - fmn.y) * 0.5f, EPSV),
            1.0f / fmaxf((fmx.z - fmn.z) * 0.5f, EPSV),
            1.0f / fmaxf((fmx.w - fmn.w) * 0.5f, EPSV));

        float* q = yg + (size_t)rb * D_DIM;
        #pragma unroll
        for (int k = 0; k < KIT; k++) {
            float4 o;
            o.x = (v[k].x - mid.x) * inv.x;
            o.y = (v[k].y - mid.y) * inv.y;
            o.z = (v[k].z - mid.z) * inv.z;
            o.w = (v[k].w - mid.w) * inv.w;
            *(float4*)(q + (size_t)k * RB * D_DIM) = o;
        }
    } else {
        // ---------------- generic two-sweep path (not hit by dataset) ------
        float4 mn = make_float4( 3.402823466e38f,  3.402823466e38f,
                                 3.402823466e38f,  3.402823466e38f);
        float4 mx = make_float4(-3.402823466e38f, -3.402823466e38f,
                                -3.402823466e38f, -3.402823466e38f);
        for (int r = rb; r < nr; r += RB) {
            float4 a = *(const float4*)(xg + (size_t)r * D_DIM);
            mn = min4(mn, a);
            mx = max4(mx, a);
        }
        s_mn[gid][rb][j] = mn;
        s_mx[gid][rb][j] = mx;
        gbar(bar);
        #pragma unroll
        for (int s = RB / 2; s >= 1; s >>= 1) {
            if (rb < s) {
                s_mn[gid][rb][j] = min4(s_mn[gid][rb][j], s_mn[gid][rb + s][j]);
                s_mx[gid][rb][j] = max4(s_mx[gid][rb][j], s_mx[gid][rb + s][j]);
            }
            gbar(bar);
        }
        float4 fmn = s_mn[gid][0][j];
        float4 fmx = s_mx[gid][0][j];
        float4 mid = make_float4((fmx.x + fmn.x) * 0.5f, (fmx.y + fmn.y) * 0.5f,
                                 (fmx.z + fmn.z) * 0.5f, (fmx.w + fmn.w) * 0.5f);
        float4 inv = make_float4(
            1.0f / fmaxf((fmx.x - fmn.x) * 0.5f, EPSV),
            1.0f / fmaxf((fmx.y - fmn.y) * 0.5f, EPSV),
            1.0f / fmaxf((fmx.z - fmn.z) * 0.5f, EPSV),
            1.0f / fmaxf((fmx.w - fmn.w) * 0.5f, EPSV));
        for (int r = rb; r < nr; r += RB) {
            float4 a = *(const float4*)(xg + (size_t)r * D_DIM);
            float4 o;
            o.x = (a.x - mid.x) * inv.x;
            o.y = (a.y - mid.y) * inv.y;
            o.z = (a.z - mid.z) * inv.z;
            o.w = (a.w - mid.w) * inv.w;
            *(float4*)(yg + (size_t)r * D_DIM) = o;
        }
    }
}

// ---------------------------------------------------------------------------
extern "C" void kernel_launch(void* const* d_in, const int* in_sizes, int n_in,
                              void* d_out, int out_size) {
    const float* x  = (const float*)d_in[0];
    const int*   bl = (const int*)d_in[1];
    float*       y  = (float*)d_out;

    const int nb   = in_sizes[1];
    const int ntot = in_sizes[0] / D_DIM;

    offsets_kernel<<<1, 1024>>>(bl, nb, ntot);

    int nbc = nb < MAXB ? nb : MAXB;
    if (nbc < 1) nbc = 1;
    const int ntiles = NCHUNK * nbc;
    const int grid = (ntiles + 1) / 2;    // 2 tiles per CTA (one per group)

    cube_norm_kernel<<<grid, NT>>>(x, y, ntiles);
}

// round 13
// speedup vs baseline: 1.2390x; 1.2390x over previous
#include <cuda_runtime.h>

// Problem constants (shapes fixed by dataset; code stays correct for any
// batch_list via the offsets kernel + generic path).
#define D_DIM   300          // embedding dim
#define DC      60           // columns per chunk (multiple of 4, divides 300)
#define DC4     (DC / 4)     // 15 float4 per row-chunk
#define NCHUNK  (D_DIM / DC) // 5
#define TR      256          // row tile (== nodes per graph in this dataset)
#define RB      16           // row-blocks
#define NT      (RB * DC4)   // 240 threads per CTA
#define KIT     (TR / RB)    // 16 rows per thread in fast path
#define MAXB    8192
#define EPSV    1e-12f

// Scratch (no cudaMalloc allowed).
__device__ int g_off[MAXB + 1];
__device__ int g_B;
__device__ int g_uni;   // 1 iff all graphs have equal node counts
__device__ int g_uval;  // that count

// ---------------------------------------------------------------------------
// Offsets kernel: detects int32 vs int64 batch_list layout. Uniform fast path
// publishes only {flag, value, count}. General path: inclusive scan to g_off.
// ---------------------------------------------------------------------------
__global__ void offsets_kernel(const int* __restrict__ p32, int nb, int ntot) {
    __shared__ int sh[1024];
    __shared__ int s_stride, s_carry, s_uni, s_val;
    const int tid = threadIdx.x;

    if (tid == 0) {
        int stride = 1;
        if (nb > 1) {
            int v0 = p32[0], v1 = p32[1];
            if (v1 == 0 && v0 != 0) stride = 2;   // int64 little-endian
        }
        s_stride = stride;
        s_carry = 0;
        s_uni = 1;
        s_val = p32[0];
        g_off[0] = 0;
        g_uni = 0;
    }
    __syncthreads();

    const int st = s_stride;
    int B = nb;
    if (B > MAXB) B = MAXB;
    const int B1 = (st == 2) ? (B >> 1) : B;
    const int v0 = s_val;

    int uni = 1;
    for (int i = tid; i < B1; i += 1024)
        if (p32[(size_t)i * st] != v0) uni = 0;
    if (!uni) atomicAnd(&s_uni, 0);
    __syncthreads();

    if (s_uni && (long long)B1 * v0 == ntot) {
        if (tid == 0) {
            g_B = B1;
            g_uval = v0;
            g_uni = 1;          // main kernel computes offsets arithmetically
        }
        return;
    }

    // ---- general path: inclusive scan into g_off ----
    for (int base = 0; base < B1; base += 1024) {
        int i = base + tid;
        int v = (i < B1) ? p32[(size_t)i * st] : 0;
        sh[tid] = v;
        __syncthreads();
        #pragma unroll
        for (int o = 1; o < 1024; o <<= 1) {
            int t = (tid >= o) ? sh[tid - o] : 0;
            __syncthreads();
            sh[tid] += t;
            __syncthreads();
        }
        if (i < B1) g_off[i + 1] = s_carry + sh[tid];
        __syncthreads();
        if (tid == 0) s_carry += sh[1023];
        __syncthreads();
    }

    int Bfinal = B1;
    if (st == 2 && B1 > 0 && g_off[B1] != ntot && B > B1) {
        for (int base = B1; base < B; base += 1024) {
            int i = base + tid;
            int v = (i < B) ? p32[(size_t)i * st] : 0;
            sh[tid] = v;
            __syncthreads();
            #pragma unroll
            for (int o = 1; o < 1024; o <<= 1) {
                int t = (tid >= o) ? sh[tid - o] : 0;
                __syncthreads();
                sh[tid] += t;
                __syncthreads();
            }
            if (i < B) g_off[i + 1] = s_carry + sh[tid];
            __syncthreads();
            if (tid == 0) s_carry += sh[1023];
            __syncthreads();
        }
        Bfinal = B;
    }
    if (tid == 0) g_B = Bfinal;
}

// ---------------------------------------------------------------------------
// Helpers
// ---------------------------------------------------------------------------
__device__ __forceinline__ float4 min4(float4 a, float4 b) {
    return make_float4(fminf(a.x, b.x), fminf(a.y, b.y),
                       fminf(a.z, b.z), fminf(a.w, b.w));
}
__device__ __forceinline__ float4 max4(float4 a, float4 b) {
    return make_float4(fmaxf(a.x, b.x), fmaxf(a.y, b.y),
                       fmaxf(a.z, b.z), fmaxf(a.w, b.w));
}
__device__ __forceinline__ void pdl_wait() {
    asm volatile("griddepcontrol.wait;" ::: "memory");
}

// ---------------------------------------------------------------------------
// Main kernel (R11 core, KIT=16): one CTA per (graph, 60-col chunk). Thread
// (rb = tid/15, j = tid%15) loads rows rb+16k of column-quad j into registers
// (16 in-flight LDG.128 per thread), reduces min/max in flight, 4-level smem
// tree fold, normalize from registers. Doubling rows-per-thread halves the
// fixed fold-bubble's share of tile time while keeping per-SM outstanding
// loads constant (15 warps x 16 == 30 warps x 8). Default cache policy so L2
// merges chunk-boundary lines. PDL: launched with programmatic stream
// serialization; waits on griddepcontrol before touching offsets state.
// ---------------------------------------------------------------------------
__global__ void __launch_bounds__(NT, 2)
cube_norm_kernel(const float* __restrict__ x, float* __restrict__ y) {
    __shared__ float4 s_mn[RB][DC4];   // 2 x 3840 B
    __shared__ float4 s_mx[RB][DC4];

    const int tid = threadIdx.x;
    const int j   = tid % DC4;         // column quad 0..14
    const int rb  = tid / DC4;         // row block 0..15
    const int g   = blockIdx.y;
    const int c0  = blockIdx.x * DC;

    pdl_wait();                        // offsets kernel results now visible

    if (g >= g_B) return;
    int r0, nr;
    if (g_uni) {
        nr = g_uval;
        r0 = g * nr;
    } else {
        r0 = g_off[g];
        nr = g_off[g + 1] - r0;
    }
    if (nr <= 0) return;

    const float* xg = x + (size_t)r0 * D_DIM + c0 + 4 * j;
    float*       yg = y + (size_t)r0 * D_DIM + c0 + 4 * j;

    if (nr == TR) {
        // ---------------- fast register-resident path ----------------
        float4 v[KIT];
        const float* p = xg + (size_t)rb * D_DIM;
        #pragma unroll
        for (int k = 0; k < KIT; k++)
            v[k] = *(const float4*)(p + (size_t)k * RB * D_DIM);

        float4 mn = v[0], mx = v[0];
        #pragma unroll
        for (int k = 1; k < KIT; k++) {
            mn = min4(mn, v[k]);
            mx = max4(mx, v[k]);
        }
        s_mn[rb][j] = mn;
        s_mx[rb][j] = mx;
        __syncthreads();

        // tree reduce over 16 row blocks (4 levels)
        #pragma unroll
        for (int s = RB / 2; s >= 1; s >>= 1) {
            if (rb < s) {
                s_mn[rb][j] = min4(s_mn[rb][j], s_mn[rb + s][j]);
                s_mx[rb][j] = max4(s_mx[rb][j], s_mx[rb + s][j]);
            }
            __syncthreads();
        }

        float4 fmn = s_mn[0][j];
        float4 fmx = s_mx[0][j];
        float4 mid = make_float4((fmx.x + fmn.x) * 0.5f, (fmx.y + fmn.y) * 0.5f,
                                 (fmx.z + fmn.z) * 0.5f, (fmx.w + fmn.w) * 0.5f);
        float4 inv = make_float4(
            1.0f / fmaxf((fmx.x - fmn.x) * 0.5f, EPSV),
            1.0f / fmaxf((fmx.y - fmn.y) * 0.5f, EPSV),
            1.0f / fmaxf((fmx.z - fmn.z) * 0.5f, EPSV),
            1.0f / fmaxf((fmx.w - fmn.w) * 0.5f, EPSV));

        float* q = yg + (size_t)rb * D_DIM;
        #pragma unroll
        for (int k = 0; k < KIT; k++) {
            float4 o;
            o.x = (v[k].x - mid.x) * inv.x;
            o.y = (v[k].y - mid.y) * inv.y;
            o.z = (v[k].z - mid.z) * inv.z;
            o.w = (v[k].w - mid.w) * inv.w;
            *(float4*)(q + (size_t)k * RB * D_DIM) = o;
        }
    } else {
        // ---------------- generic two-sweep path (not hit by dataset) ------
        float4 mn = make_float4( 3.402823466e38f,  3.402823466e38f,
                                 3.402823466e38f,  3.402823466e38f);
        float4 mx = make_float4(-3.402823466e38f, -3.402823466e38f,
                                -3.402823466e38f, -3.402823466e38f);
        for (int r = rb; r < nr; r += RB) {
            float4 a = *(const float4*)(xg + (size_t)r * D_DIM);
            mn = min4(mn, a);
            mx = max4(mx, a);
        }
        s_mn[rb][j] = mn;
        s_mx[rb][j] = mx;
        __syncthreads();
        #pragma unroll
        for (int s = RB / 2; s >= 1; s >>= 1) {
            if (rb < s) {
                s_mn[rb][j] = min4(s_mn[rb][j], s_mn[rb + s][j]);
                s_mx[rb][j] = max4(s_mx[rb][j], s_mx[rb + s][j]);
            }
            __syncthreads();
        }
        float4 fmn = s_mn[0][j];
        float4 fmx = s_mx[0][j];
        float4 mid = make_float4((fmx.x + fmn.x) * 0.5f, (fmx.y + fmn.y) * 0.5f,
                                 (fmx.z + fmn.z) * 0.5f, (fmx.w + fmn.w) * 0.5f);
        float4 inv = make_float4(
            1.0f / fmaxf((fmx.x - fmn.x) * 0.5f, EPSV),
            1.0f / fmaxf((fmx.y - fmn.y) * 0.5f, EPSV),
            1.0f / fmaxf((fmx.z - fmn.z) * 0.5f, EPSV),
            1.0f / fmaxf((fmx.w - fmn.w) * 0.5f, EPSV));
        for (int r = rb; r < nr; r += RB) {
            float4 a = *(const float4*)(xg + (size_t)r * D_DIM);
            float4 o;
            o.x = (a.x - mid.x) * inv.x;
            o.y = (a.y - mid.y) * inv.y;
            o.z = (a.z - mid.z) * inv.z;
            o.w = (a.w - mid.w) * inv.w;
            *(float4*)(yg + (size_t)r * D_DIM) = o;
        }
    }
}

// ---------------------------------------------------------------------------
extern "C" void kernel_launch(void* const* d_in, const int* in_sizes, int n_in,
                              void* d_out, int out_size) {
    const float* x  = (const float*)d_in[0];
    const int*   bl = (const int*)d_in[1];
    float*       y  = (float*)d_out;

    const int nb   = in_sizes[1];
    const int ntot = in_sizes[0] / D_DIM;

    offsets_kernel<<<1, 1024>>>(bl, nb, ntot);

    int gy = nb < MAXB ? nb : MAXB;
    if (gy < 1) gy = 1;

    // PDL: let the main kernel launch/prelude overlap the offsets kernel.
    cudaLaunchConfig_t cfg = {};
    cfg.gridDim  = dim3(NCHUNK, gy);
    cfg.blockDim = dim3(NT);
    cfg.dynamicSmemBytes = 0;
    cfg.stream = 0;
    cudaLaunchAttribute attrs[1];
    attrs[0].id = cudaLaunchAttributeProgrammaticStreamSerialization;
    attrs[0].val.programmaticStreamSerializationAllowed = 1;
    cfg.attrs = attrs;
    cfg.numAttrs = 1;
    cudaLaunchKernelEx(&cfg, cube_norm_kernel, x, y);
}

// round 14
// speedup vs baseline: 1.2728x; 1.0273x over previous
#include <cuda_runtime.h>

// Problem constants (shapes fixed by dataset; code stays correct for any
// batch_list via the offsets kernel + generic path).
#define D_DIM   300          // embedding dim
#define DC      60           // columns per chunk (multiple of 4, divides 300)
#define DC4     (DC / 4)     // 15 float4 per row-chunk
#define NCHUNK  (D_DIM / DC) // 5
#define TR      256          // row tile (== nodes per graph in this dataset)
#define RB      16           // row-blocks
#define NT      (RB * DC4)   // 240 threads per CTA
#define KIT     (TR / RB)    // 16 rows per thread in fast path
#define MAXB    8192
#define EPSV    1e-12f

// Scratch (no cudaMalloc allowed).
__device__ int g_off[MAXB + 1];
__device__ int g_B;
__device__ int g_uni;   // 1 iff all graphs have equal node counts
__device__ int g_uval;  // that count

// ---------------------------------------------------------------------------
// Offsets kernel: detects int32 vs int64 batch_list layout. Uniform fast path
// publishes only {flag, value, count}. General path: inclusive scan to g_off.
// ---------------------------------------------------------------------------
__global__ void offsets_kernel(const int* __restrict__ p32, int nb, int ntot) {
    __shared__ int sh[1024];
    __shared__ int s_stride, s_carry, s_uni, s_val;
    const int tid = threadIdx.x;

    if (tid == 0) {
        int stride = 1;
        if (nb > 1) {
            int v0 = p32[0], v1 = p32[1];
            if (v1 == 0 && v0 != 0) stride = 2;   // int64 little-endian
        }
        s_stride = stride;
        s_carry = 0;
        s_uni = 1;
        s_val = p32[0];
        g_off[0] = 0;
        g_uni = 0;
    }
    __syncthreads();

    const int st = s_stride;
    int B = nb;
    if (B > MAXB) B = MAXB;
    const int B1 = (st == 2) ? (B >> 1) : B;
    const int v0 = s_val;

    int uni = 1;
    for (int i = tid; i < B1; i += 1024)
        if (p32[(size_t)i * st] != v0) uni = 0;
    if (!uni) atomicAnd(&s_uni, 0);
    __syncthreads();

    if (s_uni && (long long)B1 * v0 == ntot) {
        if (tid == 0) {
            g_B = B1;
            g_uval = v0;
            g_uni = 1;          // main kernel computes offsets arithmetically
        }
        return;
    }

    // ---- general path: inclusive scan into g_off ----
    for (int base = 0; base < B1; base += 1024) {
        int i = base + tid;
        int v = (i < B1) ? p32[(size_t)i * st] : 0;
        sh[tid] = v;
        __syncthreads();
        #pragma unroll
        for (int o = 1; o < 1024; o <<= 1) {
            int t = (tid >= o) ? sh[tid - o] : 0;
            __syncthreads();
            sh[tid] += t;
            __syncthreads();
        }
        if (i < B1) g_off[i + 1] = s_carry + sh[tid];
        __syncthreads();
        if (tid == 0) s_carry += sh[1023];
        __syncthreads();
    }

    int Bfinal = B1;
    if (st == 2 && B1 > 0 && g_off[B1] != ntot && B > B1) {
        for (int base = B1; base < B; base += 1024) {
            int i = base + tid;
            int v = (i < B) ? p32[(size_t)i * st] : 0;
            sh[tid] = v;
            __syncthreads();
            #pragma unroll
            for (int o = 1; o < 1024; o <<= 1) {
                int t = (tid >= o) ? sh[tid - o] : 0;
                __syncthreads();
                sh[tid] += t;
                __syncthreads();
            }
            if (i < B) g_off[i + 1] = s_carry + sh[tid];
            __syncthreads();
            if (tid == 0) s_carry += sh[1023];
            __syncthreads();
        }
        Bfinal = B;
    }
    if (tid == 0) g_B = Bfinal;
}

// ---------------------------------------------------------------------------
// Helpers
// ---------------------------------------------------------------------------
__device__ __forceinline__ float4 min4(float4 a, float4 b) {
    return make_float4(fminf(a.x, b.x), fminf(a.y, b.y),
                       fminf(a.z, b.z), fminf(a.w, b.w));
}
__device__ __forceinline__ float4 max4(float4 a, float4 b) {
    return make_float4(fmaxf(a.x, b.x), fmaxf(a.y, b.y),
                       fmaxf(a.z, b.z), fmaxf(a.w, b.w));
}
__device__ __forceinline__ void pdl_wait() {
    asm volatile("griddepcontrol.wait;" ::: "memory");
}

// ---------------------------------------------------------------------------
// Main kernel (KIT=16 core, 3 CTAs/SM, 2-barrier fold): one CTA per
// (graph, 60-col chunk). Thread (rb = tid/15, j = tid%15) loads rows rb+16k
// of column-quad j into registers (16 in-flight LDG.128), reduces min/max in
// flight, writes one partial, then a single barrier + 60-thread scalar fold
// publishes mid/inv (2 barriers total vs 5 for the tree). 3 CTAs/SM (88-reg
// cap; payload 72, rest rematerializable) triples the number of independent
// barrier domains per SM so fold bubbles decorrelate. Default cache policy
// (L2 merges chunk-boundary lines). PDL overlaps launch with offsets kernel.
// ---------------------------------------------------------------------------
__global__ void __launch_bounds__(NT, 3)
cube_norm_kernel(const float* __restrict__ x, float* __restrict__ y) {
    __shared__ float pmn_s[RB * DC];   // 3840 B
    __shared__ float pmx_s[RB * DC];   // 3840 B
    __shared__ float smid[DC];
    __shared__ float sinv[DC];

    const int tid = threadIdx.x;
    const int j   = tid % DC4;         // column quad 0..14
    const int rb  = tid / DC4;         // row block 0..15
    const int g   = blockIdx.y;
    const int c0  = blockIdx.x * DC;

    pdl_wait();                        // offsets kernel results now visible

    if (g >= g_B) return;
    int r0, nr;
    if (g_uni) {
        nr = g_uval;
        r0 = g * nr;
    } else {
        r0 = g_off[g];
        nr = g_off[g + 1] - r0;
    }
    if (nr <= 0) return;

    const float* xg = x + (size_t)r0 * D_DIM + c0 + 4 * j;
    float*       yg = y + (size_t)r0 * D_DIM + c0 + 4 * j;

    if (nr == TR) {
        // ---------------- fast register-resident path ----------------
        float4 v[KIT];
        const float* p = xg + (size_t)rb * D_DIM;
        #pragma unroll
        for (int k = 0; k < KIT; k++)
            v[k] = *(const float4*)(p + (size_t)k * RB * D_DIM);

        float4 mn = v[0], mx = v[0];
        #pragma unroll
        for (int k = 1; k < KIT; k++) {
            mn = min4(mn, v[k]);
            mx = max4(mx, v[k]);
        }
        *(float4*)&pmn_s[rb * DC + 4 * j] = mn;
        *(float4*)&pmx_s[rb * DC + 4 * j] = mx;
        __syncthreads();

        // ---- fold: 60 threads, one scalar column each (conflict-free) ----
        if (tid < DC) {
            float fmn = pmn_s[tid];
            float fmx = pmx_s[tid];
            #pragma unroll
            for (int r = 1; r < RB; r++) {
                fmn = fminf(fmn, pmn_s[r * DC + tid]);
                fmx = fmaxf(fmx, pmx_s[r * DC + tid]);
            }
            smid[tid] = (fmx + fmn) * 0.5f;
            sinv[tid] = 1.0f / fmaxf((fmx - fmn) * 0.5f, EPSV);
        }
        __syncthreads();

        const float4 mid = *(const float4*)&smid[4 * j];
        const float4 inv = *(const float4*)&sinv[4 * j];

        float* q = yg + (size_t)rb * D_DIM;
        #pragma unroll
        for (int k = 0; k < KIT; k++) {
            float4 o;
            o.x = (v[k].x - mid.x) * inv.x;
            o.y = (v[k].y - mid.y) * inv.y;
            o.z = (v[k].z - mid.z) * inv.z;
            o.w = (v[k].w - mid.w) * inv.w;
            *(float4*)(q + (size_t)k * RB * D_DIM) = o;
        }
    } else {
        // ---------------- generic two-sweep path (not hit by dataset) ------
        float4 mn = make_float4( 3.402823466e38f,  3.402823466e38f,
                                 3.402823466e38f,  3.402823466e38f);
        float4 mx = make_float4(-3.402823466e38f, -3.402823466e38f,
                                -3.402823466e38f, -3.402823466e38f);
        for (int r = rb; r < nr; r += RB) {
            float4 a = *(const float4*)(xg + (size_t)r * D_DIM);
            mn = min4(mn, a);
            mx = max4(mx, a);
        }
        *(float4*)&pmn_s[rb * DC + 4 * j] = mn;
        *(float4*)&pmx_s[rb * DC + 4 * j] = mx;
        __syncthreads();
        if (tid < DC) {
            float fmn = pmn_s[tid];
            float fmx = pmx_s[tid];
            #pragma unroll
            for (int r = 1; r < RB; r++) {
                fmn = fminf(fmn, pmn_s[r * DC + tid]);
                fmx = fmaxf(fmx, pmx_s[r * DC + tid]);
            }
            smid[tid] = (fmx + fmn) * 0.5f;
            sinv[tid] = 1.0f / fmaxf((fmx - fmn) * 0.5f, EPSV);
        }
        __syncthreads();
        const float4 mid = *(const float4*)&smid[4 * j];
        const float4 inv = *(const float4*)&sinv[4 * j];
        for (int r = rb; r < nr; r += RB) {
            float4 a = *(const float4*)(xg + (size_t)r * D_DIM);
            float4 o;
            o.x = (a.x - mid.x) * inv.x;
            o.y = (a.y - mid.y) * inv.y;
            o.z = (a.z - mid.z) * inv.z;
            o.w = (a.w - mid.w) * inv.w;
            *(float4*)(yg + (size_t)r * D_DIM) = o;
        }
    }
}

// ---------------------------------------------------------------------------
extern "C" void kernel_launch(void* const* d_in, const int* in_sizes, int n_in,
                              void* d_out, int out_size) {
    const float* x  = (const float*)d_in[0];
    const int*   bl = (const int*)d_in[1];
    float*       y  = (float*)d_out;

    const int nb   = in_sizes[1];
    const int ntot = in_sizes[0] / D_DIM;

    offsets_kernel<<<1, 1024>>>(bl, nb, ntot);

    int gy = nb < MAXB ? nb : MAXB;
    if (gy < 1) gy = 1;

    // PDL: let the main kernel launch/prelude overlap the offsets kernel.
    cudaLaunchConfig_t cfg = {};
    cfg.gridDim  = dim3(NCHUNK, gy);
    cfg.blockDim = dim3(NT);
    cfg.dynamicSmemBytes = 0;
    cfg.stream = 0;
    cudaLaunchAttribute attrs[1];
    attrs[0].id = cudaLaunchAttributeProgrammaticStreamSerialization;
    attrs[0].val.programmaticStreamSerializationAllowed = 1;
    cfg.attrs = attrs;
    cfg.numAttrs = 1;
    cudaLaunchKernelEx(&cfg, cube_norm_kernel, x, y);
}